// round 1
// baseline (speedup 1.0000x reference)
#include <cuda_runtime.h>
#include <math.h>

#define HID 128
#define NMAX 50000
#define EMAX 600000

// ---------------- scratch (device globals; no runtime allocation) ----------
__device__ float g_q [NMAX * HID];
__device__ float g_k [NMAX * HID];
__device__ float g_v [NMAX * HID];
__device__ float g_y [NMAX * HID];
__device__ float g_t1[NMAX * HID];
__device__ float g_g [NMAX * HID];
__device__ float g_hc[NMAX * HID];
__device__ float g_t2[NMAX * HID];
__device__ int   g_cnt[NMAX];
__device__ int   g_off[NMAX + 1];
__device__ int   g_cur[NMAX];
__device__ int   g_ccol[EMAX];

// ---------------- CSR build -------------------------------------------------
__global__ void zero_int_kernel(int* __restrict__ p, int n) {
    int i = blockIdx.x * blockDim.x + threadIdx.x;
    if (i < n) p[i] = 0;
}

__global__ void hist_kernel(const int* __restrict__ rows, int* __restrict__ cnt, int E) {
    int e = blockIdx.x * blockDim.x + threadIdx.x;
    if (e < E) atomicAdd(&cnt[rows[e]], 1);
}

// single-block scan: off[0]=0, off[i+1]=inclusive, cur[i]=exclusive (row start)
__global__ __launch_bounds__(1024) void scan_kernel(const int* __restrict__ cnt,
                                                    int* __restrict__ off,
                                                    int* __restrict__ cur, int n) {
    __shared__ int warp_sums[32];
    __shared__ int s_carry;
    int tid = threadIdx.x, lane = tid & 31, wid = tid >> 5;
    if (tid == 0) { s_carry = 0; off[0] = 0; }
    __syncthreads();
    for (int base = 0; base < n; base += 1024) {
        int i = base + tid;
        int v = (i < n) ? cnt[i] : 0;
        int x = v;
        #pragma unroll
        for (int o = 1; o < 32; o <<= 1) {
            int t = __shfl_up_sync(0xffffffffu, x, o);
            if (lane >= o) x += t;
        }
        __syncthreads();                   // protect warp_sums from prev-iter readers
        if (lane == 31) warp_sums[wid] = x;
        __syncthreads();
        if (wid == 0) {
            int w = warp_sums[lane];
            int y = w;
            #pragma unroll
            for (int o = 1; o < 32; o <<= 1) {
                int t = __shfl_up_sync(0xffffffffu, y, o);
                if (lane >= o) y += t;
            }
            warp_sums[lane] = y - w;       // exclusive warp prefix
        }
        __syncthreads();
        int incl = x + warp_sums[wid] + s_carry;
        if (i < n) { off[i + 1] = incl; cur[i] = incl - v; }
        __syncthreads();                   // all s_carry/warp_sums reads done
        if (tid == 1023) s_carry = incl;   // chunk-inclusive total
    }
}

__global__ void scatter_kernel(const int* __restrict__ rows, const int* __restrict__ cols,
                               int* __restrict__ cur, int* __restrict__ ccol, int E) {
    int e = blockIdx.x * blockDim.x + threadIdx.x;
    if (e < E) {
        int r = rows[e];
        int p = atomicAdd(&cur[r], 1);
        ccol[p] = cols[e];                 // store col directly: no eid indirection later
    }
}

// ---------------- fused sparse attention (one warp per node) ---------------
// layout: head h owns columns c with c % 4 == h, so each float4 component = one head.
__global__ __launch_bounds__(256) void attn_kernel(
    const float* __restrict__ q, const float* __restrict__ k, const float* __restrict__ v,
    const int* __restrict__ ccol, const int* __restrict__ off,
    float* __restrict__ y, int N)
{
    int warp = (blockIdx.x * blockDim.x + threadIdx.x) >> 5;
    int lane = threadIdx.x & 31;
    if (warp >= N) return;
    int node = warp;
    int s = off[node], e = off[node + 1];

    const float4* q4 = (const float4*)q;
    const float4* k4 = (const float4*)k;
    const float4* v4 = (const float4*)v;

    float4 qv = q4[node * 32 + lane];

    float mx_x = -INFINITY, mx_y = -INFINITY, mx_z = -INFINITY, mx_w = -INFINITY;
    float l_x = 0.f, l_y = 0.f, l_z = 0.f, l_w = 0.f;
    float4 acc = make_float4(0.f, 0.f, 0.f, 0.f);

    for (int j = s; j < e; j++) {
        int c = __ldg(&ccol[j]);
        float4 kv = k4[c * 32 + lane];
        float sx = qv.x * kv.x;
        float sy = qv.y * kv.y;
        float sz = qv.z * kv.z;
        float sw = qv.w * kv.w;
        #pragma unroll
        for (int o = 16; o > 0; o >>= 1) {
            sx += __shfl_xor_sync(0xffffffffu, sx, o);
            sy += __shfl_xor_sync(0xffffffffu, sy, o);
            sz += __shfl_xor_sync(0xffffffffu, sz, o);
            sw += __shfl_xor_sync(0xffffffffu, sw, o);
        }
        float4 vv = v4[c * 32 + lane];
        // online softmax; branch is warp-uniform (all lanes hold identical s,m)
        if (sx > mx_x || sy > mx_y || sz > mx_z || sw > mx_w) {
            float nx = fmaxf(mx_x, sx), ny = fmaxf(mx_y, sy);
            float nz = fmaxf(mx_z, sz), nw = fmaxf(mx_w, sw);
            float cx = __expf(mx_x - nx), cy = __expf(mx_y - ny);
            float cz = __expf(mx_z - nz), cw = __expf(mx_w - nw);
            l_x *= cx; l_y *= cy; l_z *= cz; l_w *= cw;
            acc.x *= cx; acc.y *= cy; acc.z *= cz; acc.w *= cw;
            mx_x = nx; mx_y = ny; mx_z = nz; mx_w = nw;
        }
        float px = __expf(sx - mx_x), py = __expf(sy - mx_y);
        float pz = __expf(sz - mx_z), pw = __expf(sw - mx_w);
        l_x += px; l_y += py; l_z += pz; l_w += pw;
        acc.x += px * vv.x; acc.y += py * vv.y;
        acc.z += pz * vv.z; acc.w += pw * vv.w;
    }
    float ix = l_x > 0.f ? 1.f / l_x : 0.f;
    float iy = l_y > 0.f ? 1.f / l_y : 0.f;
    float iz = l_z > 0.f ? 1.f / l_z : 0.f;
    float iw = l_w > 0.f ? 1.f / l_w : 0.f;
    ((float4*)y)[node * 32 + lane] =
        make_float4(acc.x * ix, acc.y * iy, acc.z * iz, acc.w * iw);
}

// ---------------- SGEMM, N=128 fixed, fused epilogues -----------------------
// C[m][0:128] = epi( sum_k A[m][k] * W[k][n] + bias[n] )
// K = KT*16; for k >= 128 reads come from A2 (virtual concat), both A stride 128.
// EPI: 0 none | 1 *scale | 2 silu | 3 sigmoid | 4 C=P2+P1*val | 5 C=val+P1
template<int EPI>
__global__ __launch_bounds__(256) void sgemm_epi(
    const float* __restrict__ A1, const float* __restrict__ A2,
    const float* __restrict__ W,  const float* __restrict__ bias,
    const float* __restrict__ P1, const float* __restrict__ P2,
    float* __restrict__ C, int M, int KT, float scale)
{
    __shared__ float As[16][128];
    __shared__ float Bs[16][128];
    const int tid = threadIdx.x;
    const int bm  = blockIdx.x * 128;
    const int ty  = tid >> 4, tx = tid & 15;

    const int f0 = tid, f1 = tid + 256;
    const int ar0 = f0 >> 2, akc0 = (f0 & 3) << 2;
    const int ar1 = f1 >> 2, akc1 = (f1 & 3) << 2;
    const int br0 = f0 >> 5, bc0 = (f0 & 31) << 2;
    const int br1 = f1 >> 5, bc1 = (f1 & 31) << 2;
    const bool aok0 = (bm + ar0) < M;
    const bool aok1 = (bm + ar1) < M;

    float acc[8][8];
    #pragma unroll
    for (int i = 0; i < 8; i++)
        #pragma unroll
        for (int j = 0; j < 8; j++) acc[i][j] = 0.f;

    const float4 z4 = make_float4(0.f, 0.f, 0.f, 0.f);
    float4 ra0, ra1, rb0, rb1;

    // prefetch tile 0 (k0 = 0 -> always A1)
    ra0 = aok0 ? *(const float4*)&A1[(bm + ar0) * 128 + akc0] : z4;
    ra1 = aok1 ? *(const float4*)&A1[(bm + ar1) * 128 + akc1] : z4;
    rb0 = *(const float4*)&W[br0 * 128 + bc0];
    rb1 = *(const float4*)&W[br1 * 128 + bc1];

    for (int kt = 0; kt < KT; kt++) {
        __syncthreads();
        As[akc0 + 0][ar0] = ra0.x; As[akc0 + 1][ar0] = ra0.y;
        As[akc0 + 2][ar0] = ra0.z; As[akc0 + 3][ar0] = ra0.w;
        As[akc1 + 0][ar1] = ra1.x; As[akc1 + 1][ar1] = ra1.y;
        As[akc1 + 2][ar1] = ra1.z; As[akc1 + 3][ar1] = ra1.w;
        *(float4*)&Bs[br0][bc0] = rb0;
        *(float4*)&Bs[br1][bc1] = rb1;
        __syncthreads();

        if (kt + 1 < KT) {   // prefetch next tile before compute (hide gmem latency)
            int k0 = (kt + 1) * 16;
            const float* Ap = (k0 < 128) ? A1 : A2;
            int kb = (k0 < 128) ? k0 : (k0 - 128);
            ra0 = aok0 ? *(const float4*)&Ap[(bm + ar0) * 128 + kb + akc0] : z4;
            ra1 = aok1 ? *(const float4*)&Ap[(bm + ar1) * 128 + kb + akc1] : z4;
            rb0 = *(const float4*)&W[(k0 + br0) * 128 + bc0];
            rb1 = *(const float4*)&W[(k0 + br1) * 128 + bc1];
        }

        #pragma unroll
        for (int kk = 0; kk < 16; kk++) {
            float4 a0 = *(const float4*)&As[kk][ty * 8];
            float4 a1 = *(const float4*)&As[kk][ty * 8 + 4];
            float4 b0 = *(const float4*)&Bs[kk][tx * 8];
            float4 b1 = *(const float4*)&Bs[kk][tx * 8 + 4];
            float a[8] = {a0.x, a0.y, a0.z, a0.w, a1.x, a1.y, a1.z, a1.w};
            float b[8] = {b0.x, b0.y, b0.z, b0.w, b1.x, b1.y, b1.z, b1.w};
            #pragma unroll
            for (int i = 0; i < 8; i++)
                #pragma unroll
                for (int j = 0; j < 8; j++)
                    acc[i][j] += a[i] * b[j];
        }
    }

    const int cn0 = tx * 8;
    #pragma unroll
    for (int i = 0; i < 8; i++) {
        int cm = bm + ty * 8 + i;
        if (cm < M) {
            #pragma unroll
            for (int j4 = 0; j4 < 8; j4 += 4) {
                float vals[4];
                #pragma unroll
                for (int c = 0; c < 4; c++) {
                    float val = acc[i][j4 + c] + __ldg(&bias[cn0 + j4 + c]);
                    if (EPI == 1) val *= scale;
                    if (EPI == 2) val = val / (1.f + __expf(-val));   // silu
                    if (EPI == 3) val = 1.f / (1.f + __expf(-val));   // sigmoid
                    vals[c] = val;
                }
                int idx = cm * 128 + cn0 + j4;
                if (EPI == 4) {
                    float4 gm = *(const float4*)&P1[idx];
                    float4 hp = *(const float4*)&P2[idx];
                    vals[0] = hp.x + gm.x * vals[0];
                    vals[1] = hp.y + gm.y * vals[1];
                    vals[2] = hp.z + gm.z * vals[2];
                    vals[3] = hp.w + gm.w * vals[3];
                } else if (EPI == 5) {
                    float4 ad = *(const float4*)&P1[idx];
                    vals[0] += ad.x; vals[1] += ad.y;
                    vals[2] += ad.z; vals[3] += ad.w;
                }
                *(float4*)&C[idx] = make_float4(vals[0], vals[1], vals[2], vals[3]);
            }
        }
    }
}

// ---------------- launch ----------------------------------------------------
extern "C" void kernel_launch(void* const* d_in, const int* in_sizes, int n_in,
                              void* d_out, int out_size) {
    const float* h_prev = (const float*)d_in[0];
    const float* h_pred = (const float*)d_in[1];
    const float* Wq  = (const float*)d_in[2];  const float* bq  = (const float*)d_in[3];
    const float* Wk  = (const float*)d_in[4];  const float* bk  = (const float*)d_in[5];
    const float* Wv  = (const float*)d_in[6];  const float* bv  = (const float*)d_in[7];
    const float* Wo  = (const float*)d_in[8];  const float* bo  = (const float*)d_in[9];
    const float* Wg1 = (const float*)d_in[10]; const float* bg1 = (const float*)d_in[11];
    const float* Wg2 = (const float*)d_in[12]; const float* bg2 = (const float*)d_in[13];
    const float* Wm1 = (const float*)d_in[14]; const float* bm1 = (const float*)d_in[15];
    const float* Wm2 = (const float*)d_in[16]; const float* bm2 = (const float*)d_in[17];
    const int* rows  = (const int*)d_in[18];
    const int* cols  = (const int*)d_in[19];
    const int N = in_sizes[0] / HID;
    const int E = in_sizes[18];
    float* out = (float*)d_out;

    float *q, *k, *v, *y, *t1, *g, *hc, *t2;
    int *cnt, *off, *cur, *ccol;
    cudaGetSymbolAddress((void**)&q,   g_q);
    cudaGetSymbolAddress((void**)&k,   g_k);
    cudaGetSymbolAddress((void**)&v,   g_v);
    cudaGetSymbolAddress((void**)&y,   g_y);
    cudaGetSymbolAddress((void**)&t1,  g_t1);
    cudaGetSymbolAddress((void**)&g,   g_g);
    cudaGetSymbolAddress((void**)&hc,  g_hc);
    cudaGetSymbolAddress((void**)&t2,  g_t2);
    cudaGetSymbolAddress((void**)&cnt, g_cnt);
    cudaGetSymbolAddress((void**)&off, g_off);
    cudaGetSymbolAddress((void**)&cur, g_cur);
    cudaGetSymbolAddress((void**)&ccol, g_ccol);

    const int gb = (N + 127) / 128;
    const float qscale = 0.17677669529663687f;   // 1/sqrt(32)

    // CSR build
    zero_int_kernel<<<(N + 255) / 256, 256>>>(cnt, N);
    hist_kernel<<<(E + 255) / 256, 256>>>(rows, cnt, E);
    scan_kernel<<<1, 1024>>>(cnt, off, cur, N);
    scatter_kernel<<<(E + 255) / 256, 256>>>(rows, cols, cur, ccol, E);

    // projections (q pre-scaled in epilogue)
    sgemm_epi<1><<<gb, 256>>>(h_pred, nullptr, Wq, bq, nullptr, nullptr, q, N, 8, qscale);
    sgemm_epi<0><<<gb, 256>>>(h_prev, nullptr, Wk, bk, nullptr, nullptr, k, N, 8, 1.f);
    sgemm_epi<0><<<gb, 256>>>(h_pred, nullptr, Wv, bv, nullptr, nullptr, v, N, 8, 1.f);

    // sparse multi-head attention
    attn_kernel<<<(N + 7) / 8, 256>>>(q, k, v, ccol, off, y, N);

    // gate: g = sigmoid(silu([h_pred,h_prev]@Wg1+bg1)@Wg2+bg2)
    sgemm_epi<2><<<gb, 256>>>(h_pred, h_prev, Wg1, bg1, nullptr, nullptr, t1, N, 16, 1.f);
    sgemm_epi<3><<<gb, 256>>>(t1, nullptr, Wg2, bg2, nullptr, nullptr, g, N, 8, 1.f);

    // h_corr = h_prev + g * (y@Wo + bo)
    sgemm_epi<4><<<gb, 256>>>(y, nullptr, Wo, bo, g, h_prev, hc, N, 8, 1.f);

    // fused = h_corr + silu([h_corr,h_prev]@Wm1+bm1)@Wm2+bm2
    sgemm_epi<2><<<gb, 256>>>(hc, h_prev, Wm1, bm1, nullptr, nullptr, t2, N, 16, 1.f);
    sgemm_epi<5><<<gb, 256>>>(t2, nullptr, Wm2, bm2, hc, nullptr, out, N, 8, 1.f);
}

// round 3
// speedup vs baseline: 1.3987x; 1.3987x over previous
#include <cuda_runtime.h>
#include <cuda_bf16.h>
#include <cstdint>
#include <math.h>

#define HID 128
#define NMAX 50000
#define EMAX 600000

// ---------------- scratch (device globals; no runtime allocation) ----------
__device__ float g_q [NMAX * HID];
__device__ float g_k [NMAX * HID];
__device__ float g_v [NMAX * HID];
__device__ float g_y [NMAX * HID];
__device__ float g_t1[NMAX * HID];
__device__ float g_g [NMAX * HID];
__device__ float g_hc[NMAX * HID];
__device__ float g_t2[NMAX * HID];
__device__ int   g_cnt[NMAX];
__device__ int   g_off[NMAX + 1];
__device__ int   g_cur[NMAX];
__device__ int   g_ccol[EMAX];
// pre-converted weights, [N=128][K] K-major, row stride 272B (128 bf16 + 16B pad)
// per 128-K chunk: 34816B hi image || 34816B lo image = 69632B; 10 chunks total
__device__ __align__(16) unsigned char g_wpre[696320];

#define CHUNK_B   69632
#define IMG_B     34816
#define ROW_B     272

// ---------------- helpers ---------------------------------------------------
__device__ __forceinline__ uint32_t smem_u32(const void* p) {
    uint32_t a;
    asm("{ .reg .u64 t; cvta.to.shared.u64 t, %1; cvt.u32.u64 %0, t; }" : "=r"(a) : "l"(p));
    return a;
}
__device__ __forceinline__ uint32_t pk(float a, float b) {
    __nv_bfloat162 t = __floats2bfloat162_rn(a, b);
    return *reinterpret_cast<uint32_t*>(&t);
}
__device__ __forceinline__ void ldsm4(uint32_t& r0, uint32_t& r1, uint32_t& r2, uint32_t& r3,
                                      uint32_t addr) {
    asm volatile("ldmatrix.sync.aligned.m8n8.x4.shared.b16 {%0,%1,%2,%3}, [%4];"
                 : "=r"(r0), "=r"(r1), "=r"(r2), "=r"(r3) : "r"(addr));
}
__device__ __forceinline__ void mma16816(float* d, const uint32_t* a, uint32_t b0, uint32_t b1) {
    asm volatile(
        "mma.sync.aligned.m16n8k16.row.col.f32.bf16.bf16.f32 "
        "{%0,%1,%2,%3}, {%4,%5,%6,%7}, {%8,%9}, {%0,%1,%2,%3};"
        : "+f"(d[0]), "+f"(d[1]), "+f"(d[2]), "+f"(d[3])
        : "r"(a[0]), "r"(a[1]), "r"(a[2]), "r"(a[3]), "r"(b0), "r"(b1));
}

// ---------------- weight pre-convert: W[K][128] -> [n][k] hi/lo, padded -----
__global__ void wconv_kernel(const float* __restrict__ W, int K, unsigned char* __restrict__ dst) {
    int idx = blockIdx.x * blockDim.x + threadIdx.x;   // idx = kp*128 + n
    int total = K * 64;
    if (idx >= total) return;
    int n = idx & 127;
    int k = (idx >> 7) << 1;
    int c = k >> 7, kl = k & 127;
    float w0 = W[k * 128 + n], w1 = W[(k + 1) * 128 + n];
    float h0 = __bfloat162float(__float2bfloat16(w0));
    float h1 = __bfloat162float(__float2bfloat16(w1));
    unsigned char* base = dst + c * CHUNK_B + n * ROW_B + kl * 2;
    *(uint32_t*)(base)         = pk(h0, h1);
    *(uint32_t*)(base + IMG_B) = pk(w0 - h0, w1 - h1);
}

// ---------------- CSR build -------------------------------------------------
__global__ void zero_int_kernel(int* __restrict__ p, int n) {
    int i = blockIdx.x * blockDim.x + threadIdx.x;
    if (i < n) p[i] = 0;
}
__global__ void hist_kernel(const int* __restrict__ rows, int* __restrict__ cnt, int E) {
    int e = blockIdx.x * blockDim.x + threadIdx.x;
    if (e < E) atomicAdd(&cnt[rows[e]], 1);
}
__global__ __launch_bounds__(1024) void scan_kernel(const int* __restrict__ cnt,
                                                    int* __restrict__ off,
                                                    int* __restrict__ cur, int n) {
    __shared__ int warp_sums[32];
    __shared__ int s_carry;
    int tid = threadIdx.x, lane = tid & 31, wid = tid >> 5;
    if (tid == 0) { s_carry = 0; off[0] = 0; }
    __syncthreads();
    for (int base = 0; base < n; base += 1024) {
        int i = base + tid;
        int v = (i < n) ? cnt[i] : 0;
        int x = v;
        #pragma unroll
        for (int o = 1; o < 32; o <<= 1) {
            int t = __shfl_up_sync(0xffffffffu, x, o);
            if (lane >= o) x += t;
        }
        __syncthreads();
        if (lane == 31) warp_sums[wid] = x;
        __syncthreads();
        if (wid == 0) {
            int w = warp_sums[lane];
            int y = w;
            #pragma unroll
            for (int o = 1; o < 32; o <<= 1) {
                int t = __shfl_up_sync(0xffffffffu, y, o);
                if (lane >= o) y += t;
            }
            warp_sums[lane] = y - w;
        }
        __syncthreads();
        int incl = x + warp_sums[wid] + s_carry;
        if (i < n) { off[i + 1] = incl; cur[i] = incl - v; }
        __syncthreads();
        if (tid == 1023) s_carry = incl;
    }
}
__global__ void scatter_kernel(const int* __restrict__ rows, const int* __restrict__ cols,
                               int* __restrict__ cur, int* __restrict__ ccol, int E) {
    int e = blockIdx.x * blockDim.x + threadIdx.x;
    if (e < E) {
        int r = rows[e];
        int p = atomicAdd(&cur[r], 1);
        ccol[p] = cols[e];
    }
}

// ---------------- fused sparse attention (one warp per node) ---------------
__global__ __launch_bounds__(256) void attn_kernel(
    const float* __restrict__ q, const float* __restrict__ k, const float* __restrict__ v,
    const int* __restrict__ ccol, const int* __restrict__ off,
    float* __restrict__ y, int N)
{
    int warp = (blockIdx.x * blockDim.x + threadIdx.x) >> 5;
    int lane = threadIdx.x & 31;
    if (warp >= N) return;
    int node = warp;
    int s = off[node], e = off[node + 1];

    const float4* q4 = (const float4*)q;
    const float4* k4 = (const float4*)k;
    const float4* v4 = (const float4*)v;

    float4 qv = q4[node * 32 + lane];

    float mx_x = -INFINITY, mx_y = -INFINITY, mx_z = -INFINITY, mx_w = -INFINITY;
    float l_x = 0.f, l_y = 0.f, l_z = 0.f, l_w = 0.f;
    float4 acc = make_float4(0.f, 0.f, 0.f, 0.f);

    for (int j = s; j < e; j++) {
        int c = __ldg(&ccol[j]);
        float4 kv = k4[c * 32 + lane];
        float sx = qv.x * kv.x;
        float sy = qv.y * kv.y;
        float sz = qv.z * kv.z;
        float sw = qv.w * kv.w;
        #pragma unroll
        for (int o = 16; o > 0; o >>= 1) {
            sx += __shfl_xor_sync(0xffffffffu, sx, o);
            sy += __shfl_xor_sync(0xffffffffu, sy, o);
            sz += __shfl_xor_sync(0xffffffffu, sz, o);
            sw += __shfl_xor_sync(0xffffffffu, sw, o);
        }
        float4 vv = v4[c * 32 + lane];
        if (sx > mx_x || sy > mx_y || sz > mx_z || sw > mx_w) {
            float nx = fmaxf(mx_x, sx), ny = fmaxf(mx_y, sy);
            float nz = fmaxf(mx_z, sz), nw = fmaxf(mx_w, sw);
            float cx = __expf(mx_x - nx), cy = __expf(mx_y - ny);
            float cz = __expf(mx_z - nz), cw = __expf(mx_w - nw);
            l_x *= cx; l_y *= cy; l_z *= cz; l_w *= cw;
            acc.x *= cx; acc.y *= cy; acc.z *= cz; acc.w *= cw;
            mx_x = nx; mx_y = ny; mx_z = nz; mx_w = nw;
        }
        float px = __expf(sx - mx_x), py = __expf(sy - mx_y);
        float pz = __expf(sz - mx_z), pw = __expf(sw - mx_w);
        l_x += px; l_y += py; l_z += pz; l_w += pw;
        acc.x += px * vv.x; acc.y += py * vv.y;
        acc.z += pz * vv.z; acc.w += pw * vv.w;
    }
    float ix = l_x > 0.f ? 1.f / l_x : 0.f;
    float iy = l_y > 0.f ? 1.f / l_y : 0.f;
    float iz = l_z > 0.f ? 1.f / l_z : 0.f;
    float iw = l_w > 0.f ? 1.f / l_w : 0.f;
    ((float4*)y)[node * 32 + lane] =
        make_float4(acc.x * ix, acc.y * iy, acc.z * iz, acc.w * iw);
}

// ---------------- HMMA bf16-split GEMM, N=128, fused epilogues --------------
// C[m][0:128] = epi( sum_k A[m][k]*W[k][n] + bias[n] ), K = nchunk*128
// chunk 0 reads A1, chunk 1 reads A2 (virtual concat), both stride 128.
// Bpre: pre-converted [n][k] hi/lo bf16 image, 272B row stride, 69632B/chunk.
// EPI: 0 none | 1 *scale | 2 silu | 3 sigmoid | 4 C=P2+P1*val | 5 C=val+P1
#define SM_AH 0
#define SM_AL 34816
#define SM_BH 69632
#define SM_BL 104448
#define SMEM_TOTAL 139264

template<int EPI>
__global__ __launch_bounds__(256, 1) void tgemm(
    const float* __restrict__ A1, const float* __restrict__ A2,
    const unsigned char* __restrict__ Bpre, const float* __restrict__ bias,
    const float* __restrict__ P1, const float* __restrict__ P2,
    float* __restrict__ C, int M, int nchunk, float scale)
{
    extern __shared__ char smem[];
    const uint32_t sb = smem_u32(smem);
    const int tid = threadIdx.x, wid = tid >> 5, lane = tid & 31;
    const int bm = blockIdx.x * 128;
    const int wm = (wid & 3) * 32;     // warp m-base in tile
    const int wn = (wid >> 2) * 64;    // warp n-base in tile

    const int arow = tid >> 1;
    const int ac0  = (tid & 1) * 64;
    const bool aok = (bm + arow) < M;

    // ldmatrix per-thread byte offsets (stride 272B, quad-pair layout)
    const int lrow = lane & 15, lcol16 = (lane >> 4) * 16;
    uint32_t addrA[2], addrB[4];
    #pragma unroll
    for (int mt = 0; mt < 2; mt++)
        addrA[mt] = sb + (uint32_t)((wm + mt * 16 + lrow) * ROW_B + lcol16);
    #pragma unroll
    for (int j = 0; j < 4; j++)
        addrB[j] = sb + (uint32_t)((wn + j * 16 + lrow) * ROW_B + lcol16);

    float acc[2][8][4];
    #pragma unroll
    for (int mt = 0; mt < 2; mt++)
        #pragma unroll
        for (int nt = 0; nt < 8; nt++)
            #pragma unroll
            for (int r = 0; r < 4; r++) acc[mt][nt][r] = 0.f;

    for (int c = 0; c < nchunk; c++) {
        if (c) __syncthreads();
        // stage B: straight copy of pre-converted chunk (hi||lo = 69632 B)
        {
            const uint4* bp = (const uint4*)(Bpre + c * CHUNK_B);
            uint4* bs = (uint4*)(smem + SM_BH);
            #pragma unroll
            for (int i = 0; i < 17; i++) bs[tid + i * 256] = bp[tid + i * 256];
        }
        // stage A: fp32 -> bf16 hi/lo into padded rows
        {
            const float* Ap = (c == 0) ? A1 : A2;
            unsigned char* ah = (unsigned char*)smem + SM_AH + arow * ROW_B;
            unsigned char* al = (unsigned char*)smem + SM_AL + arow * ROW_B;
            #pragma unroll
            for (int i = 0; i < 16; i++) {
                int col = ac0 + i * 4;
                float4 a = aok ? *(const float4*)&Ap[(bm + arow) * 128 + col]
                               : make_float4(0.f, 0.f, 0.f, 0.f);
                float hx = __bfloat162float(__float2bfloat16(a.x));
                float hy = __bfloat162float(__float2bfloat16(a.y));
                float hz = __bfloat162float(__float2bfloat16(a.z));
                float hw = __bfloat162float(__float2bfloat16(a.w));
                *(uint32_t*)(ah + col * 2)     = pk(hx, hy);
                *(uint32_t*)(ah + col * 2 + 4) = pk(hz, hw);
                *(uint32_t*)(al + col * 2)     = pk(a.x - hx, a.y - hy);
                *(uint32_t*)(al + col * 2 + 4) = pk(a.z - hz, a.w - hw);
            }
        }
        __syncthreads();

        #pragma unroll
        for (int ks = 0; ks < 8; ks++) {
            const uint32_t kb = (uint32_t)(ks * 32);   // k0*2 bytes
            uint32_t ah[2][4], al[2][4], bh[8][2], bl[8][2];
            #pragma unroll
            for (int mt = 0; mt < 2; mt++) {
                ldsm4(ah[mt][0], ah[mt][1], ah[mt][2], ah[mt][3], addrA[mt] + SM_AH + kb);
                ldsm4(al[mt][0], al[mt][1], al[mt][2], al[mt][3], addrA[mt] + SM_AL + kb);
            }
            #pragma unroll
            for (int j = 0; j < 4; j++) {
                uint32_t r0, r1, r2, r3;
                ldsm4(r0, r1, r2, r3, addrB[j] + SM_BH + kb);
                bh[2*j][0] = r0; bh[2*j+1][0] = r1; bh[2*j][1] = r2; bh[2*j+1][1] = r3;
                ldsm4(r0, r1, r2, r3, addrB[j] + SM_BL + kb);
                bl[2*j][0] = r0; bl[2*j+1][0] = r1; bl[2*j][1] = r2; bl[2*j+1][1] = r3;
            }
            #pragma unroll
            for (int mt = 0; mt < 2; mt++)
                #pragma unroll
                for (int nt = 0; nt < 8; nt++) {
                    mma16816(acc[mt][nt], ah[mt], bh[nt][0], bh[nt][1]);  // hi*hi
                    mma16816(acc[mt][nt], ah[mt], bl[nt][0], bl[nt][1]);  // hi*lo
                    mma16816(acc[mt][nt], al[mt], bh[nt][0], bh[nt][1]);  // lo*hi
                }
        }
    }

    // epilogue straight from register accumulators
    #pragma unroll
    for (int mt = 0; mt < 2; mt++) {
        #pragma unroll
        for (int half = 0; half < 2; half++) {
            int row = bm + wm + mt * 16 + (lane >> 2) + half * 8;
            if (row < M) {
                #pragma unroll
                for (int nt = 0; nt < 8; nt++) {
                    int col = wn + nt * 8 + 2 * (lane & 3);
                    float2 bs = *(const float2*)&bias[col];
                    float v0 = acc[mt][nt][half * 2 + 0] + bs.x;
                    float v1 = acc[mt][nt][half * 2 + 1] + bs.y;
                    if (EPI == 1) { v0 *= scale; v1 *= scale; }
                    if (EPI == 2) { v0 = v0 / (1.f + __expf(-v0)); v1 = v1 / (1.f + __expf(-v1)); }
                    if (EPI == 3) { v0 = 1.f / (1.f + __expf(-v0)); v1 = 1.f / (1.f + __expf(-v1)); }
                    int idx = row * 128 + col;
                    if (EPI == 4) {
                        float2 gm = *(const float2*)&P1[idx];
                        float2 hp = *(const float2*)&P2[idx];
                        v0 = hp.x + gm.x * v0;
                        v1 = hp.y + gm.y * v1;
                    } else if (EPI == 5) {
                        float2 ad = *(const float2*)&P1[idx];
                        v0 += ad.x; v1 += ad.y;
                    }
                    *(float2*)&C[idx] = make_float2(v0, v1);
                }
            }
        }
    }
}

// ---------------- launch ----------------------------------------------------
extern "C" void kernel_launch(void* const* d_in, const int* in_sizes, int n_in,
                              void* d_out, int out_size) {
    const float* h_prev = (const float*)d_in[0];
    const float* h_pred = (const float*)d_in[1];
    const float* Wq  = (const float*)d_in[2];  const float* bq  = (const float*)d_in[3];
    const float* Wk  = (const float*)d_in[4];  const float* bk  = (const float*)d_in[5];
    const float* Wv  = (const float*)d_in[6];  const float* bv  = (const float*)d_in[7];
    const float* Wo  = (const float*)d_in[8];  const float* bo  = (const float*)d_in[9];
    const float* Wg1 = (const float*)d_in[10]; const float* bg1 = (const float*)d_in[11];
    const float* Wg2 = (const float*)d_in[12]; const float* bg2 = (const float*)d_in[13];
    const float* Wm1 = (const float*)d_in[14]; const float* bm1 = (const float*)d_in[15];
    const float* Wm2 = (const float*)d_in[16]; const float* bm2 = (const float*)d_in[17];
    const int* rows  = (const int*)d_in[18];
    const int* cols  = (const int*)d_in[19];
    const int N = in_sizes[0] / HID;
    const int E = in_sizes[18];
    float* out = (float*)d_out;

    float *q, *k, *v, *y, *t1, *g, *hc, *t2;
    int *cnt, *off, *cur, *ccol;
    unsigned char* wpre;
    cudaGetSymbolAddress((void**)&q,   g_q);
    cudaGetSymbolAddress((void**)&k,   g_k);
    cudaGetSymbolAddress((void**)&v,   g_v);
    cudaGetSymbolAddress((void**)&y,   g_y);
    cudaGetSymbolAddress((void**)&t1,  g_t1);
    cudaGetSymbolAddress((void**)&g,   g_g);
    cudaGetSymbolAddress((void**)&hc,  g_hc);
    cudaGetSymbolAddress((void**)&t2,  g_t2);
    cudaGetSymbolAddress((void**)&cnt, g_cnt);
    cudaGetSymbolAddress((void**)&off, g_off);
    cudaGetSymbolAddress((void**)&cur, g_cur);
    cudaGetSymbolAddress((void**)&ccol, g_ccol);
    cudaGetSymbolAddress((void**)&wpre, g_wpre);

    // weight image offsets (chunks of 69632 B)
    unsigned char* pWq  = wpre;
    unsigned char* pWk  = wpre + 1 * CHUNK_B;
    unsigned char* pWv  = wpre + 2 * CHUNK_B;
    unsigned char* pWo  = wpre + 3 * CHUNK_B;
    unsigned char* pWg2 = wpre + 4 * CHUNK_B;
    unsigned char* pWm2 = wpre + 5 * CHUNK_B;
    unsigned char* pWg1 = wpre + 6 * CHUNK_B;   // 2 chunks
    unsigned char* pWm1 = wpre + 8 * CHUNK_B;   // 2 chunks

    cudaFuncSetAttribute(tgemm<0>, cudaFuncAttributeMaxDynamicSharedMemorySize, SMEM_TOTAL);
    cudaFuncSetAttribute(tgemm<1>, cudaFuncAttributeMaxDynamicSharedMemorySize, SMEM_TOTAL);
    cudaFuncSetAttribute(tgemm<2>, cudaFuncAttributeMaxDynamicSharedMemorySize, SMEM_TOTAL);
    cudaFuncSetAttribute(tgemm<3>, cudaFuncAttributeMaxDynamicSharedMemorySize, SMEM_TOTAL);
    cudaFuncSetAttribute(tgemm<4>, cudaFuncAttributeMaxDynamicSharedMemorySize, SMEM_TOTAL);
    cudaFuncSetAttribute(tgemm<5>, cudaFuncAttributeMaxDynamicSharedMemorySize, SMEM_TOTAL);

    const int gb = (N + 127) / 128;
    const float qscale = 0.17677669529663687f;   // 1/sqrt(32)

    // CSR build
    zero_int_kernel<<<(N + 255) / 256, 256>>>(cnt, N);
    hist_kernel<<<(E + 255) / 256, 256>>>(rows, cnt, E);
    scan_kernel<<<1, 1024>>>(cnt, off, cur, N);
    scatter_kernel<<<(E + 255) / 256, 256>>>(rows, cols, cur, ccol, E);

    // weight pre-convert (hi/lo bf16, [n][k] padded image)
    wconv_kernel<<<32, 256>>>(Wq,  128, pWq);
    wconv_kernel<<<32, 256>>>(Wk,  128, pWk);
    wconv_kernel<<<32, 256>>>(Wv,  128, pWv);
    wconv_kernel<<<32, 256>>>(Wo,  128, pWo);
    wconv_kernel<<<32, 256>>>(Wg2, 128, pWg2);
    wconv_kernel<<<32, 256>>>(Wm2, 128, pWm2);
    wconv_kernel<<<64, 256>>>(Wg1, 256, pWg1);
    wconv_kernel<<<64, 256>>>(Wm1, 256, pWm1);

    // projections (q pre-scaled in epilogue)
    tgemm<1><<<gb, 256, SMEM_TOTAL>>>(h_pred, nullptr, pWq, bq, nullptr, nullptr, q, N, 1, qscale);
    tgemm<0><<<gb, 256, SMEM_TOTAL>>>(h_prev, nullptr, pWk, bk, nullptr, nullptr, k, N, 1, 1.f);
    tgemm<0><<<gb, 256, SMEM_TOTAL>>>(h_pred, nullptr, pWv, bv, nullptr, nullptr, v, N, 1, 1.f);

    // sparse multi-head attention
    attn_kernel<<<(N + 7) / 8, 256>>>(q, k, v, ccol, off, y, N);

    // gate: g = sigmoid(silu([h_pred,h_prev]@Wg1+bg1)@Wg2+bg2)
    tgemm<2><<<gb, 256, SMEM_TOTAL>>>(h_pred, h_prev, pWg1, bg1, nullptr, nullptr, t1, N, 2, 1.f);
    tgemm<3><<<gb, 256, SMEM_TOTAL>>>(t1, nullptr, pWg2, bg2, nullptr, nullptr, g, N, 1, 1.f);

    // h_corr = h_prev + g * (y@Wo + bo)
    tgemm<4><<<gb, 256, SMEM_TOTAL>>>(y, nullptr, pWo, bo, g, h_prev, hc, N, 1, 1.f);

    // fused = h_corr + silu([h_corr,h_prev]@Wm1+bm1)@Wm2+bm2
    tgemm<2><<<gb, 256, SMEM_TOTAL>>>(hc, h_prev, pWm1, bm1, nullptr, nullptr, t2, N, 2, 1.f);
    tgemm<5><<<gb, 256, SMEM_TOTAL>>>(t2, nullptr, pWm2, bm2, hc, nullptr, out, N, 1, 1.f);
}

// round 4
// speedup vs baseline: 1.7663x; 1.2628x over previous
#include <cuda_runtime.h>
#include <cuda_bf16.h>
#include <cstdint>
#include <math.h>

#define HID 128
#define NMAX 50000
#define NPAD 50048          // 391*128, covers last tile
#define EMAX 600000
#define IMG_ROW 512         // image row: 256B hi || 256B lo
#define SM_ROW 144          // smem row stride (conflict-free for ldmatrix)
#define SM_IMG 18432        // 128*144
#define SM_BUF 73728        // 4 regions (Ahi,Alo,Bhi,Blo)
#define SMEM_TOTAL 147456   // double buffered

// ---------------- scratch (device globals) ----------------------------------
__device__ float g_q [NMAX * HID];
__device__ float g_k [NMAX * HID];
__device__ float g_v [NMAX * HID];
__device__ float g_g [NMAX * HID];
__device__ float g_hc[NMAX * HID];
__device__ __align__(16) unsigned char g_ipred[(size_t)NPAD * IMG_ROW];
__device__ __align__(16) unsigned char g_iprev[(size_t)NPAD * IMG_ROW];
__device__ __align__(16) unsigned char g_iy  [(size_t)NPAD * IMG_ROW];
__device__ __align__(16) unsigned char g_it1 [(size_t)NPAD * IMG_ROW];
__device__ __align__(16) unsigned char g_it2 [(size_t)NPAD * IMG_ROW];
__device__ __align__(16) unsigned char g_ihc [(size_t)NPAD * IMG_ROW];
__device__ __align__(16) unsigned char g_wpre[10 * 65536];   // 10 weight chunks
__device__ int g_cnt[NMAX];
__device__ int g_linc[NMAX];
__device__ int g_bsum[256];
__device__ int g_bofs[256];
__device__ int g_start[NMAX];
__device__ int g_cur[NMAX];
__device__ int g_ccol[EMAX];

// ---------------- helpers ----------------------------------------------------
__device__ __forceinline__ uint32_t smem_u32(const void* p) {
    uint32_t a;
    asm("{ .reg .u64 t; cvta.to.shared.u64 t, %1; cvt.u32.u64 %0, t; }" : "=r"(a) : "l"(p));
    return a;
}
__device__ __forceinline__ uint32_t pk(float a, float b) {
    __nv_bfloat162 t = __floats2bfloat162_rn(a, b);
    return *reinterpret_cast<uint32_t*>(&t);
}
__device__ __forceinline__ float bf16r(float x) {
    return __bfloat162float(__float2bfloat16(x));
}
__device__ __forceinline__ void ldsm4(uint32_t& r0, uint32_t& r1, uint32_t& r2, uint32_t& r3,
                                      uint32_t addr) {
    asm volatile("ldmatrix.sync.aligned.m8n8.x4.shared.b16 {%0,%1,%2,%3}, [%4];"
                 : "=r"(r0), "=r"(r1), "=r"(r2), "=r"(r3) : "r"(addr));
}
__device__ __forceinline__ void mma16816(float* d, const uint32_t* a, uint32_t b0, uint32_t b1) {
    asm volatile(
        "mma.sync.aligned.m16n8k16.row.col.f32.bf16.bf16.f32 "
        "{%0,%1,%2,%3}, {%4,%5,%6,%7}, {%8,%9}, {%0,%1,%2,%3};"
        : "+f"(d[0]), "+f"(d[1]), "+f"(d[2]), "+f"(d[3])
        : "r"(a[0]), "r"(a[1]), "r"(a[2]), "r"(a[3]), "r"(b0), "r"(b1));
}
__device__ __forceinline__ void cp16(uint32_t saddr, const void* gaddr) {
    asm volatile("cp.async.cg.shared.global [%0], [%1], 16;" :: "r"(saddr), "l"(gaddr));
}

// ---------------- input convert: fp32 -> hi/lo image ------------------------
__global__ void hconv_kernel(const float* __restrict__ hp, const float* __restrict__ hv,
                             unsigned char* __restrict__ ip, unsigned char* __restrict__ iv,
                             int n) {
    int idx = blockIdx.x * blockDim.x + threadIdx.x;
    if (idx >= n * 32) return;
    const float* src = blockIdx.y ? hv : hp;
    unsigned char* dst = blockIdx.y ? iv : ip;
    int row = idx >> 5, sg = idx & 31;
    float4 a = *(const float4*)&src[row * 128 + sg * 4];
    float hx = bf16r(a.x), hy = bf16r(a.y), hz = bf16r(a.z), hw = bf16r(a.w);
    unsigned char* r = dst + (size_t)row * IMG_ROW + sg * 8;
    *(uint2*)(r)       = make_uint2(pk(hx, hy), pk(hz, hw));
    *(uint2*)(r + 256) = make_uint2(pk(a.x - hx, a.y - hy), pk(a.z - hz, a.w - hw));
}

// ---------------- weight convert: all 10 chunks in one launch ----------------
struct WArg { const float* W[10]; };
__global__ void wconv_kernel(WArg a, unsigned char* __restrict__ dst) {
    int slot = blockIdx.y;
    int idx = blockIdx.x * blockDim.x + threadIdx.x;   // 0..8191
    int n = idx & 127, kp = idx >> 7;                  // kp 0..63
    int kof = (slot == 7 || slot == 9) ? 128 : 0;
    const float* W = a.W[slot];
    int k = kof + kp * 2;
    float w0 = W[k * 128 + n], w1 = W[(k + 1) * 128 + n];
    float h0 = bf16r(w0), h1 = bf16r(w1);
    unsigned char* base = dst + slot * 65536 + n * IMG_ROW + kp * 4;
    *(uint32_t*)(base)       = pk(h0, h1);
    *(uint32_t*)(base + 256) = pk(w0 - h0, w1 - h1);
}

// ---------------- CSR build --------------------------------------------------
__global__ void zero_int_kernel(int* __restrict__ p, int n) {
    int i = blockIdx.x * blockDim.x + threadIdx.x;
    if (i < n) p[i] = 0;
}
__global__ void hist_kernel(const int* __restrict__ rows, int* __restrict__ cnt, int E) {
    int e = blockIdx.x * blockDim.x + threadIdx.x;
    if (e < E) atomicAdd(&cnt[rows[e]], 1);
}
__device__ __forceinline__ int wscan_incl(int x, int lane) {
    #pragma unroll
    for (int o = 1; o < 32; o <<= 1) {
        int t = __shfl_up_sync(0xffffffffu, x, o);
        if (lane >= o) x += t;
    }
    return x;
}
__device__ __forceinline__ int bscan256(int v, int* ws, int tid) {
    int lane = tid & 31, w = tid >> 5;
    int x = wscan_incl(v, lane);
    if (lane == 31) ws[w] = x;
    __syncthreads();
    if (tid < 8) {
        int s = ws[tid];
        #pragma unroll
        for (int o = 1; o < 8; o <<= 1) {
            int t = __shfl_up_sync(0xffu, s, o);
            if (tid >= o) s += t;
        }
        ws[tid] = s;
    }
    __syncthreads();
    return x + (w ? ws[w - 1] : 0);
}
__global__ __launch_bounds__(256) void scan1_kernel(const int* __restrict__ cnt,
                                                    int* __restrict__ linc,
                                                    int* __restrict__ bsum, int n) {
    __shared__ int ws[8];
    int tid = threadIdx.x, i = blockIdx.x * 256 + tid;
    int v = (i < n) ? cnt[i] : 0;
    int incl = bscan256(v, ws, tid);
    if (i < n) linc[i] = incl;
    if (tid == 255) bsum[blockIdx.x] = incl;
}
__global__ __launch_bounds__(256) void scan2_kernel(const int* __restrict__ bsum,
                                                    int* __restrict__ bofs, int nb) {
    __shared__ int ws[8];
    int tid = threadIdx.x;
    int v = (tid < nb) ? bsum[tid] : 0;
    int incl = bscan256(v, ws, tid);
    if (tid < nb) bofs[tid] = incl - v;   // exclusive
}
__global__ void scan3_kernel(const int* __restrict__ bofs, const int* __restrict__ linc,
                             const int* __restrict__ cnt, int* __restrict__ start,
                             int* __restrict__ cur, int n) {
    int i = blockIdx.x * 256 + threadIdx.x;
    if (i < n) {
        int s = bofs[blockIdx.x] + linc[i] - cnt[i];
        start[i] = s;
        cur[i] = s;
    }
}
__global__ void scatter_kernel(const int* __restrict__ rows, const int* __restrict__ cols,
                               int* __restrict__ cur, int* __restrict__ ccol, int E) {
    int e = blockIdx.x * blockDim.x + threadIdx.x;
    if (e < E) {
        int r = rows[e];
        int p = atomicAdd(&cur[r], 1);
        ccol[p] = cols[e];
    }
}

// ---------------- fused sparse attention (one warp per node) -----------------
// reads q,k,v fp32; writes y as hi/lo bf16 image (GEMM input for Wo)
__global__ __launch_bounds__(256) void attn_kernel(
    const float* __restrict__ q, const float* __restrict__ k, const float* __restrict__ v,
    const int* __restrict__ ccol, const int* __restrict__ start, const int* __restrict__ cnt,
    unsigned char* __restrict__ yimg, int N)
{
    int warp = (blockIdx.x * blockDim.x + threadIdx.x) >> 5;
    int lane = threadIdx.x & 31;
    if (warp >= N) return;
    int node = warp;
    int s = start[node], e = s + cnt[node];

    const float4* q4 = (const float4*)q;
    const float4* k4 = (const float4*)k;
    const float4* v4 = (const float4*)v;

    float4 qv = q4[node * 32 + lane];

    float mx_x = -INFINITY, mx_y = -INFINITY, mx_z = -INFINITY, mx_w = -INFINITY;
    float l_x = 0.f, l_y = 0.f, l_z = 0.f, l_w = 0.f;
    float4 acc = make_float4(0.f, 0.f, 0.f, 0.f);

    for (int j = s; j < e; j++) {
        int c = __ldg(&ccol[j]);
        float4 kv = k4[c * 32 + lane];
        float sx = qv.x * kv.x;
        float sy = qv.y * kv.y;
        float sz = qv.z * kv.z;
        float sw = qv.w * kv.w;
        #pragma unroll
        for (int o = 16; o > 0; o >>= 1) {
            sx += __shfl_xor_sync(0xffffffffu, sx, o);
            sy += __shfl_xor_sync(0xffffffffu, sy, o);
            sz += __shfl_xor_sync(0xffffffffu, sz, o);
            sw += __shfl_xor_sync(0xffffffffu, sw, o);
        }
        float4 vv = v4[c * 32 + lane];
        if (sx > mx_x || sy > mx_y || sz > mx_z || sw > mx_w) {
            float nx = fmaxf(mx_x, sx), ny = fmaxf(mx_y, sy);
            float nz = fmaxf(mx_z, sz), nw = fmaxf(mx_w, sw);
            float cx = __expf(mx_x - nx), cy = __expf(mx_y - ny);
            float cz = __expf(mx_z - nz), cw = __expf(mx_w - nw);
            l_x *= cx; l_y *= cy; l_z *= cz; l_w *= cw;
            acc.x *= cx; acc.y *= cy; acc.z *= cz; acc.w *= cw;
            mx_x = nx; mx_y = ny; mx_z = nz; mx_w = nw;
        }
        float px = __expf(sx - mx_x), py = __expf(sy - mx_y);
        float pz = __expf(sz - mx_z), pw = __expf(sw - mx_w);
        l_x += px; l_y += py; l_z += pz; l_w += pw;
        acc.x += px * vv.x; acc.y += py * vv.y;
        acc.z += pz * vv.z; acc.w += pw * vv.w;
    }
    float ox = acc.x * (l_x > 0.f ? 1.f / l_x : 0.f);
    float oy = acc.y * (l_y > 0.f ? 1.f / l_y : 0.f);
    float oz = acc.z * (l_z > 0.f ? 1.f / l_z : 0.f);
    float ow = acc.w * (l_w > 0.f ? 1.f / l_w : 0.f);
    float hx = bf16r(ox), hy = bf16r(oy), hz = bf16r(oz), hw = bf16r(ow);
    unsigned char* yr = yimg + (size_t)node * IMG_ROW + lane * 8;
    *(uint2*)(yr)       = make_uint2(pk(hx, hy), pk(hz, hw));
    *(uint2*)(yr + 256) = make_uint2(pk(ox - hx, oy - hy), pk(oz - hz, ow - hw));
}

// ---------------- pipelined HMMA bf16-split GEMM -----------------------------
// A,B are hi/lo images (IMG_ROW 512B rows). K = nchunk*128, 2 substages/chunk.
// EPI: 1 *scale | 2 silu | 3 sigmoid | 4 C=P2+P1*val | 5 C=val+P1
// WF: write fp32 Cf, WI: write hi/lo image Cimg
__device__ __forceinline__ void stage_cp(uint32_t sbuf, const unsigned char* Aimg,
                                         const unsigned char* Bc, int h, int tid, int bm) {
    #pragma unroll
    for (int i = 0; i < 16; i++) {
        int t = tid + i * 256;
        int region = t >> 10, row = (t >> 3) & 127, sg = t & 7;
        int lo = (region & 1) * 256;
        const unsigned char* g = (region < 2)
            ? Aimg + (size_t)(bm + row) * IMG_ROW + lo + h * 128 + sg * 16
            : Bc   + row * IMG_ROW + lo + h * 128 + sg * 16;
        cp16(sbuf + region * SM_IMG + row * SM_ROW + sg * 16, g);
    }
    asm volatile("cp.async.commit_group;" ::: "memory");
}

template<int EPI, int WF, int WI>
__device__ __forceinline__ void gemm_body(
    const unsigned char* __restrict__ A1, const unsigned char* __restrict__ A2,
    const unsigned char* __restrict__ B, const float* __restrict__ bias,
    const float* __restrict__ P1, const float* __restrict__ P2,
    float* __restrict__ Cf, unsigned char* __restrict__ Cimg,
    int M, int nchunk, float scale, char* smem, int bm)
{
    const uint32_t sb = smem_u32(smem);
    const int tid = threadIdx.x, wid = tid >> 5, lane = tid & 31;
    const int wm = (wid & 3) * 32, wn = (wid >> 2) * 64;
    const int S = nchunk * 2;

    float acc[2][8][4];
    #pragma unroll
    for (int mt = 0; mt < 2; mt++)
        #pragma unroll
        for (int nt = 0; nt < 8; nt++)
            #pragma unroll
            for (int r = 0; r < 4; r++) acc[mt][nt][r] = 0.f;

    stage_cp(sb, A1, B, 0, tid, bm);
    {
        const unsigned char* Ai = (S > 2 && 1 >= 2) ? A2 : A1;  // s=1 -> chunk0
        stage_cp(sb + SM_BUF, Ai, B, 1, tid, bm);
    }

    const int lrow = lane & 15, lc16 = (lane >> 4) * 16;

    for (int s = 0; s < S; s++) {
        if (s + 1 < S) asm volatile("cp.async.wait_group 1;" ::: "memory");
        else           asm volatile("cp.async.wait_group 0;" ::: "memory");
        __syncthreads();
        const uint32_t base = sb + (s & 1) * SM_BUF;
        #pragma unroll
        for (int ks = 0; ks < 4; ks++) {
            const uint32_t kb = (uint32_t)(ks * 32);
            uint32_t ah[2][4], al[2][4], bh[8][2], bl[8][2];
            #pragma unroll
            for (int mt = 0; mt < 2; mt++) {
                uint32_t ad = base + (wm + mt * 16 + lrow) * SM_ROW + lc16 + kb;
                ldsm4(ah[mt][0], ah[mt][1], ah[mt][2], ah[mt][3], ad);
                ldsm4(al[mt][0], al[mt][1], al[mt][2], al[mt][3], ad + SM_IMG);
            }
            #pragma unroll
            for (int j = 0; j < 4; j++) {
                uint32_t bd = base + 2 * SM_IMG + (wn + j * 16 + lrow) * SM_ROW + lc16 + kb;
                uint32_t r0, r1, r2, r3;
                ldsm4(r0, r1, r2, r3, bd);
                bh[2*j][0] = r0; bh[2*j+1][0] = r1; bh[2*j][1] = r2; bh[2*j+1][1] = r3;
                ldsm4(r0, r1, r2, r3, bd + SM_IMG);
                bl[2*j][0] = r0; bl[2*j+1][0] = r1; bl[2*j][1] = r2; bl[2*j+1][1] = r3;
            }
            #pragma unroll
            for (int mt = 0; mt < 2; mt++)
                #pragma unroll
                for (int nt = 0; nt < 8; nt++) {
                    mma16816(acc[mt][nt], ah[mt], bh[nt][0], bh[nt][1]);
                    mma16816(acc[mt][nt], ah[mt], bl[nt][0], bl[nt][1]);
                    mma16816(acc[mt][nt], al[mt], bh[nt][0], bh[nt][1]);
                }
        }
        __syncthreads();
        if (s + 2 < S) {
            int ns = s + 2;
            const unsigned char* Ai = (ns >= 2) ? A2 : A1;
            stage_cp(sb + (s & 1) * SM_BUF, Ai, B + (ns >> 1) * 65536, ns & 1, tid, bm);
        }
    }

    // epilogue from register accumulators
    #pragma unroll
    for (int mt = 0; mt < 2; mt++) {
        #pragma unroll
        for (int half = 0; half < 2; half++) {
            int row = bm + wm + mt * 16 + (lane >> 2) + half * 8;
            if (row < M) {
                #pragma unroll
                for (int nt = 0; nt < 8; nt++) {
                    int col = wn + nt * 8 + 2 * (lane & 3);
                    float2 bs = *(const float2*)&bias[col];
                    float v0 = acc[mt][nt][half * 2 + 0] + bs.x;
                    float v1 = acc[mt][nt][half * 2 + 1] + bs.y;
                    if (EPI == 1) { v0 *= scale; v1 *= scale; }
                    if (EPI == 2) { v0 = v0 / (1.f + __expf(-v0)); v1 = v1 / (1.f + __expf(-v1)); }
                    if (EPI == 3) { v0 = 1.f / (1.f + __expf(-v0)); v1 = 1.f / (1.f + __expf(-v1)); }
                    int idx = row * 128 + col;
                    if (EPI == 4) {
                        float2 gm = *(const float2*)&P1[idx];
                        float2 hp = *(const float2*)&P2[idx];
                        v0 = hp.x + gm.x * v0;
                        v1 = hp.y + gm.y * v1;
                    } else if (EPI == 5) {
                        float2 ad = *(const float2*)&P1[idx];
                        v0 += ad.x; v1 += ad.y;
                    }
                    if (WF) *(float2*)&Cf[idx] = make_float2(v0, v1);
                    if (WI) {
                        float h0 = bf16r(v0), h1 = bf16r(v1);
                        unsigned char* r = Cimg + (size_t)row * IMG_ROW + col * 2;
                        *(uint32_t*)(r)       = pk(h0, h1);
                        *(uint32_t*)(r + 256) = pk(v0 - h0, v1 - h1);
                    }
                }
            }
        }
    }
}

template<int EPI, int WF, int WI>
__global__ __launch_bounds__(256, 1) void tgemm(
    const unsigned char* __restrict__ A1, const unsigned char* __restrict__ A2,
    const unsigned char* __restrict__ B, const float* __restrict__ bias,
    const float* __restrict__ P1, const float* __restrict__ P2,
    float* __restrict__ Cf, unsigned char* __restrict__ Cimg,
    int M, int nchunk, float scale)
{
    extern __shared__ char smem[];
    gemm_body<EPI, WF, WI>(A1, A2, B, bias, P1, P2, Cf, Cimg, M, nchunk, scale,
                           smem, blockIdx.x * 128);
}

__global__ __launch_bounds__(256, 1) void qkv_kernel(
    const unsigned char* __restrict__ ipred, const unsigned char* __restrict__ iprev,
    const unsigned char* __restrict__ wpre,
    const float* __restrict__ bq, const float* __restrict__ bk, const float* __restrict__ bv,
    float* __restrict__ q, float* __restrict__ k, float* __restrict__ v,
    int M, float qs)
{
    extern __shared__ char smem[];
    int y = blockIdx.y;
    const unsigned char* A = (y == 1) ? iprev : ipred;
    const unsigned char* B = wpre + y * 65536;
    const float* bias = (y == 0) ? bq : (y == 1) ? bk : bv;
    float* C = (y == 0) ? q : (y == 1) ? k : v;
    float sc = (y == 0) ? qs : 1.f;
    gemm_body<1, 1, 0>(A, nullptr, B, bias, nullptr, nullptr, C, nullptr, M, 1, sc,
                       smem, blockIdx.x * 128);
}

// ---------------- launch -----------------------------------------------------
extern "C" void kernel_launch(void* const* d_in, const int* in_sizes, int n_in,
                              void* d_out, int out_size) {
    const float* h_prev = (const float*)d_in[0];
    const float* h_pred = (const float*)d_in[1];
    const float* Wq  = (const float*)d_in[2];  const float* bq  = (const float*)d_in[3];
    const float* Wk  = (const float*)d_in[4];  const float* bk  = (const float*)d_in[5];
    const float* Wv  = (const float*)d_in[6];  const float* bv  = (const float*)d_in[7];
    const float* Wo  = (const float*)d_in[8];  const float* bo  = (const float*)d_in[9];
    const float* Wg1 = (const float*)d_in[10]; const float* bg1 = (const float*)d_in[11];
    const float* Wg2 = (const float*)d_in[12]; const float* bg2 = (const float*)d_in[13];
    const float* Wm1 = (const float*)d_in[14]; const float* bm1 = (const float*)d_in[15];
    const float* Wm2 = (const float*)d_in[16]; const float* bm2 = (const float*)d_in[17];
    const int* rows  = (const int*)d_in[18];
    const int* cols  = (const int*)d_in[19];
    const int N = in_sizes[0] / HID;
    const int E = in_sizes[18];
    float* out = (float*)d_out;

    float *q, *k, *v, *g, *hc;
    int *cnt, *linc, *bsum, *bofs, *start, *cur, *ccol;
    unsigned char *ipred, *iprev, *iy, *it1, *it2, *ihc, *wpre;
    cudaGetSymbolAddress((void**)&q,   g_q);
    cudaGetSymbolAddress((void**)&k,   g_k);
    cudaGetSymbolAddress((void**)&v,   g_v);
    cudaGetSymbolAddress((void**)&g,   g_g);
    cudaGetSymbolAddress((void**)&hc,  g_hc);
    cudaGetSymbolAddress((void**)&ipred, g_ipred);
    cudaGetSymbolAddress((void**)&iprev, g_iprev);
    cudaGetSymbolAddress((void**)&iy,  g_iy);
    cudaGetSymbolAddress((void**)&it1, g_it1);
    cudaGetSymbolAddress((void**)&it2, g_it2);
    cudaGetSymbolAddress((void**)&ihc, g_ihc);
    cudaGetSymbolAddress((void**)&wpre, g_wpre);
    cudaGetSymbolAddress((void**)&cnt, g_cnt);
    cudaGetSymbolAddress((void**)&linc, g_linc);
    cudaGetSymbolAddress((void**)&bsum, g_bsum);
    cudaGetSymbolAddress((void**)&bofs, g_bofs);
    cudaGetSymbolAddress((void**)&start, g_start);
    cudaGetSymbolAddress((void**)&cur, g_cur);
    cudaGetSymbolAddress((void**)&ccol, g_ccol);

    cudaFuncSetAttribute(qkv_kernel,     cudaFuncAttributeMaxDynamicSharedMemorySize, SMEM_TOTAL);
    cudaFuncSetAttribute(tgemm<2, 0, 1>, cudaFuncAttributeMaxDynamicSharedMemorySize, SMEM_TOTAL);
    cudaFuncSetAttribute(tgemm<3, 1, 0>, cudaFuncAttributeMaxDynamicSharedMemorySize, SMEM_TOTAL);
    cudaFuncSetAttribute(tgemm<4, 1, 1>, cudaFuncAttributeMaxDynamicSharedMemorySize, SMEM_TOTAL);
    cudaFuncSetAttribute(tgemm<5, 1, 0>, cudaFuncAttributeMaxDynamicSharedMemorySize, SMEM_TOTAL);

    const int gb = (N + 127) / 128;
    const int nb = (N + 255) / 256;
    const float qscale = 0.17677669529663687f;   // 1/sqrt(32)

    // CSR build (deterministic multiblock scan)
    zero_int_kernel<<<(N + 255) / 256, 256>>>(cnt, N);
    hist_kernel<<<(E + 255) / 256, 256>>>(rows, cnt, E);
    scan1_kernel<<<nb, 256>>>(cnt, linc, bsum, N);
    scan2_kernel<<<1, 256>>>(bsum, bofs, nb);
    scan3_kernel<<<nb, 256>>>(bofs, linc, cnt, start, cur, N);
    scatter_kernel<<<(E + 255) / 256, 256>>>(rows, cols, cur, ccol, E);

    // input + weight image conversion
    hconv_kernel<<<dim3((N * 32 + 255) / 256, 2), 256>>>(h_pred, h_prev, ipred, iprev, N);
    WArg wa;
    wa.W[0] = Wq;  wa.W[1] = Wk;  wa.W[2] = Wv;  wa.W[3] = Wo;
    wa.W[4] = Wg2; wa.W[5] = Wm2; wa.W[6] = Wg1; wa.W[7] = Wg1;
    wa.W[8] = Wm1; wa.W[9] = Wm1;
    wconv_kernel<<<dim3(32, 10), 256>>>(wa, wpre);

    // q,k,v projections in one launch (q pre-scaled)
    qkv_kernel<<<dim3(gb, 3), 256, SMEM_TOTAL>>>(ipred, iprev, wpre, bq, bk, bv,
                                                 q, k, v, N, qscale);

    // sparse multi-head attention -> y image
    attn_kernel<<<(N + 7) / 8, 256>>>(q, k, v, ccol, start, cnt, iy, N);

    // gate: t1 = silu([h_pred,h_prev]@Wg1+bg1) (img); g = sigmoid(t1@Wg2+bg2)
    tgemm<2, 0, 1><<<gb, 256, SMEM_TOTAL>>>(ipred, iprev, wpre + 6 * 65536, bg1,
                                            nullptr, nullptr, nullptr, it1, N, 2, 1.f);
    tgemm<3, 1, 0><<<gb, 256, SMEM_TOTAL>>>(it1, nullptr, wpre + 4 * 65536, bg2,
                                            nullptr, nullptr, g, nullptr, N, 1, 1.f);

    // h_corr = h_prev + g * (y@Wo + bo)  (fp32 + img)
    tgemm<4, 1, 1><<<gb, 256, SMEM_TOTAL>>>(iy, nullptr, wpre + 3 * 65536, bo,
                                            g, h_prev, hc, ihc, N, 1, 1.f);

    // fused = h_corr + silu([h_corr,h_prev]@Wm1+bm1)@Wm2+bm2
    tgemm<2, 0, 1><<<gb, 256, SMEM_TOTAL>>>(ihc, iprev, wpre + 8 * 65536, bm1,
                                            nullptr, nullptr, nullptr, it2, N, 2, 1.f);
    tgemm<5, 1, 0><<<gb, 256, SMEM_TOTAL>>>(it2, nullptr, wpre + 5 * 65536, bm2,
                                            hc, nullptr, out, nullptr, N, 1, 1.f);
}